// round 1
// baseline (speedup 1.0000x reference)
#include <cuda_runtime.h>
#include <cuda_bf16.h>
#include <math.h>

#define NB 4096
#define NL 8192
#define NT 256

// Per-row partials (scratch; __device__ globals are the allowed scratch path).
__device__ float g_bce[NB];
__device__ int   g_tp[NB];
__device__ int   g_tn[NB];
__device__ int   g_gp[NB];

__device__ __forceinline__ void acc_elem(float p, float t,
                                         float& bce, int& tp, int& tn, int& gp) {
    // torch.where(isnan|isinf, 0, pred)
    if (!isfinite(p)) p = 0.0f;
    bool tb = (t > 0.0f);          // truth is exactly 0.0 or 1.0
    // bce = -(t*log(p) + (1-t)*log(1-p)); since t in {0,1}, select one branch.
    float x  = tb ? p : (1.0f - p);
    float lg = fmaxf(__logf(x), -100.0f);   // __logf(0) = -inf -> clamped to -100
    bce -= lg;
    bool pb = (p > 0.5f);
    tp += (int)(pb && tb);
    tn += (int)(!pb && !tb);
    gp += (int)tb;
}

__global__ void __launch_bounds__(NT) row_kernel(const float* __restrict__ pred,
                                                 const float* __restrict__ truth,
                                                 const int*   __restrict__ lengths) {
    const int row = blockIdx.x;
    const int len = lengths[row];
    const size_t off = (size_t)row * NL;
    const float4* __restrict__ p4 = reinterpret_cast<const float4*>(pred + off);
    const float4* __restrict__ t4 = reinterpret_cast<const float4*>(truth + off);

    float bce = 0.0f;
    int tp = 0, tn = 0, gp = 0;

    const int n4 = len >> 2;   // full float4 groups inside the valid prefix
    for (int i = threadIdx.x; i < n4; i += NT) {
        float4 p = p4[i];
        float4 t = t4[i];
        acc_elem(p.x, t.x, bce, tp, tn, gp);
        acc_elem(p.y, t.y, bce, tp, tn, gp);
        acc_elem(p.z, t.z, bce, tp, tn, gp);
        acc_elem(p.w, t.w, bce, tp, tn, gp);
    }
    // scalar tail (len % 4 elements)
    const int base = n4 << 2;
    const int rem  = len - base;
    if ((int)threadIdx.x < rem) {
        acc_elem(pred[off + base + threadIdx.x],
                 truth[off + base + threadIdx.x], bce, tp, tn, gp);
    }

    // warp reduce
    #pragma unroll
    for (int s = 16; s > 0; s >>= 1) {
        bce += __shfl_down_sync(0xffffffffu, bce, s);
        tp  += __shfl_down_sync(0xffffffffu, tp,  s);
        tn  += __shfl_down_sync(0xffffffffu, tn,  s);
        gp  += __shfl_down_sync(0xffffffffu, gp,  s);
    }
    __shared__ float s_bce[NT / 32];
    __shared__ int   s_tp[NT / 32], s_tn[NT / 32], s_gp[NT / 32];
    const int wid = threadIdx.x >> 5, lid = threadIdx.x & 31;
    if (lid == 0) { s_bce[wid] = bce; s_tp[wid] = tp; s_tn[wid] = tn; s_gp[wid] = gp; }
    __syncthreads();
    if (threadIdx.x == 0) {
        float b = 0.0f; int a = 0, c = 0, d = 0;
        #pragma unroll
        for (int w = 0; w < NT / 32; w++) { b += s_bce[w]; a += s_tp[w]; c += s_tn[w]; d += s_gp[w]; }
        g_bce[row] = b; g_tp[row] = a; g_tn[row] = c; g_gp[row] = d;
    }
}

__global__ void __launch_bounds__(1024) finalize_kernel(const int* __restrict__ lengths,
                                                        float* __restrict__ out,
                                                        int out_size) {
    const int tid = threadIdx.x;
    float loss = 0.0f;
    long long tp = 0, tn = 0, gp = 0, valid = 0;
    for (int r = tid; r < NB; r += 1024) {
        const int len = lengths[r];
        if (len > 0) loss += g_bce[r] / (float)len;   // per-seq mean, empty rows contribute 0
        tp += g_tp[r]; tn += g_tn[r]; gp += g_gp[r]; valid += len;
    }
    // warp reduce
    #pragma unroll
    for (int s = 16; s > 0; s >>= 1) {
        loss  += __shfl_down_sync(0xffffffffu, loss,  s);
        tp    += __shfl_down_sync(0xffffffffu, tp,    s);
        tn    += __shfl_down_sync(0xffffffffu, tn,    s);
        gp    += __shfl_down_sync(0xffffffffu, gp,    s);
        valid += __shfl_down_sync(0xffffffffu, valid, s);
    }
    __shared__ float     sl[32];
    __shared__ long long stp[32], stn[32], sgp[32], sv[32];
    const int wid = tid >> 5, lid = tid & 31;
    if (lid == 0) { sl[wid] = loss; stp[wid] = tp; stn[wid] = tn; sgp[wid] = gp; sv[wid] = valid; }
    __syncthreads();
    if (tid == 0) {
        float L = 0.0f; long long TP = 0, TN = 0, GP = 0, V = 0;
        #pragma unroll
        for (int w = 0; w < 32; w++) { L += sl[w]; TP += stp[w]; TN += stn[w]; GP += sgp[w]; V += sv[w]; }
        long long GN = V - GP;                 // gn = valid & !targ
        if (GP < 1) GP = 1;
        if (GN < 1) GN = 1;
        float lossf = L / (float)NB;
        float acc   = ((float)TP / (float)GP) * ((float)TN / (float)GN);
        out[0] = lossf;
        if (out_size > 1) out[1] = acc;
    }
}

extern "C" void kernel_launch(void* const* d_in, const int* in_sizes, int n_in,
                              void* d_out, int out_size) {
    const float* pred    = (const float*)d_in[0];
    const float* truth   = (const float*)d_in[1];
    const int*   lengths = (const int*)d_in[2];
    float* out = (float*)d_out;

    row_kernel<<<NB, NT>>>(pred, truth, lengths);
    finalize_kernel<<<1, 1024>>>(lengths, out, out_size);
}